// round 1
// baseline (speedup 1.0000x reference)
#include <cuda_runtime.h>
#include <math.h>

#define BATCH 32
#define HW    56
#define DIMC  192
#define LTOK  (HW*HW)            /* 3136 */
#define MROWS (BATCH*LTOK)       /* 100352 */
#define NHEAD 6
#define HD    32
#define WS    7
#define NWROW 8                  /* windows per row = 56/7 */
#define NWIN  (BATCH*NWROW*NWROW)/* 2048 */
#define HIDDEN 768
#define SS    3

// ---------------- scratch (static device memory; no allocs) ----------------
__device__ float g_xn   [(size_t)MROWS * DIMC];     // normalized tokens (window order / x order)
__device__ float g_qkv  [(size_t)MROWS * 3 * DIMC]; // qkv in window order
__device__ float g_attn [(size_t)MROWS * DIMC];     // attention output, window order
__device__ float g_x    [(size_t)MROWS * DIMC];     // x after proj + reverse shift (x order)
__device__ float g_hid  [(size_t)MROWS * HIDDEN];   // MLP hidden

// window-order row -> x-order row; same map serves gather and scatter
__device__ __forceinline__ int winrow_to_xrow(int r) {
    int win = r / 49, n = r % 49;
    int bb = win >> 6;
    int wrem = win & 63;
    int wh = wrem >> 3, ww = wrem & 7;
    int i = n / 7, j = n % 7;
    int h = wh * 7 + i + SS; if (h >= HW) h -= HW;
    int w = ww * 7 + j + SS; if (w >= HW) w -= HW;
    return bb * LTOK + h * HW + w;
}

// ---------------- LayerNorm (optionally with shifted-window gather) ---------
template<bool GATHER>
__global__ void ln_kernel(const float* __restrict__ x,
                          const float* __restrict__ g,
                          const float* __restrict__ b,
                          float* __restrict__ out) {
    int row  = blockIdx.x * 8 + (threadIdx.x >> 5);
    int lane = threadIdx.x & 31;
    int srow = GATHER ? winrow_to_xrow(row) : row;
    const float* src = x + (size_t)srow * DIMC;

    float v[6];
    float sum = 0.f;
#pragma unroll
    for (int t = 0; t < 6; t++) { v[t] = src[lane + 32 * t]; sum += v[t]; }
#pragma unroll
    for (int o = 16; o > 0; o >>= 1) sum += __shfl_xor_sync(0xffffffffu, sum, o);
    float mu = sum * (1.f / DIMC);
    float vs = 0.f;
#pragma unroll
    for (int t = 0; t < 6; t++) { float d = v[t] - mu; vs += d * d; }
#pragma unroll
    for (int o = 16; o > 0; o >>= 1) vs += __shfl_xor_sync(0xffffffffu, vs, o);
    float inv = rsqrtf(vs * (1.f / DIMC) + 1e-5f);

    float* dst = out + (size_t)row * DIMC;
#pragma unroll
    for (int t = 0; t < 6; t++) {
        int c = lane + 32 * t;
        dst[c] = (v[t] - mu) * inv * g[c] + b[c];
    }
}

// ---------------- per-(window,head) attention ------------------------------
__global__ void attn_kernel(const float* __restrict__ qkv, float* __restrict__ out) {
    int win = blockIdx.x, head = blockIdx.y;
    int tid = threadIdx.x;

    __shared__ float sq[49][33], sk[49][33], sv[49][33];
    __shared__ float ss[49][49];

    const float* base = qkv + (size_t)win * 49 * (3 * DIMC) + head * HD;
    for (int idx = tid; idx < 49 * 8; idx += blockDim.x) {
        int n = idx >> 3, d4 = idx & 7;
        const float* row = base + (size_t)n * (3 * DIMC);
        float4 q4 = *(const float4*)(row + d4 * 4);
        float4 k4 = *(const float4*)(row + DIMC + d4 * 4);
        float4 v4 = *(const float4*)(row + 2 * DIMC + d4 * 4);
        sq[n][d4*4+0]=q4.x; sq[n][d4*4+1]=q4.y; sq[n][d4*4+2]=q4.z; sq[n][d4*4+3]=q4.w;
        sk[n][d4*4+0]=k4.x; sk[n][d4*4+1]=k4.y; sk[n][d4*4+2]=k4.z; sk[n][d4*4+3]=k4.w;
        sv[n][d4*4+0]=v4.x; sv[n][d4*4+1]=v4.y; sv[n][d4*4+2]=v4.z; sv[n][d4*4+3]=v4.w;
    }
    __syncthreads();

    const float scale = 0.17677669529663687f; // 32^-0.5
    for (int idx = tid; idx < 49 * 49; idx += blockDim.x) {
        int n = idx / 49, m = idx % 49;
        float acc = 0.f;
#pragma unroll
        for (int d = 0; d < HD; d++) acc += sq[n][d] * sk[m][d];
        ss[n][m] = acc * scale;
    }
    __syncthreads();

    if (tid < 49) {
        float mx = -1e30f;
#pragma unroll 7
        for (int m = 0; m < 49; m++) mx = fmaxf(mx, ss[tid][m]);
        float sum = 0.f;
#pragma unroll 7
        for (int m = 0; m < 49; m++) { float e = __expf(ss[tid][m] - mx); ss[tid][m] = e; sum += e; }
        float inv = 1.f / sum;
#pragma unroll 7
        for (int m = 0; m < 49; m++) ss[tid][m] *= inv;
    }
    __syncthreads();

    float* obase = out + (size_t)win * 49 * DIMC + head * HD;
    for (int idx = tid; idx < 49 * HD; idx += blockDim.x) {
        int n = idx >> 5, d = idx & 31;
        float acc = 0.f;
#pragma unroll 7
        for (int m = 0; m < 49; m++) acc += ss[n][m] * sv[m][d];
        obase[(size_t)n * DIMC + d] = acc;
    }
}

// ---------------- SGEMM: C[M,N] = A[M,K] @ B[K,N] + bias, fused epilogues --
// EPI: 0 = bias only; 1 = bias + scatter (window row -> x row); 2 = bias + gelu;
//      3 = bias + residual add (res has row stride N)
template<int EPI>
__global__ __launch_bounds__(256)
void sgemm_kernel(const float* __restrict__ A, const float* __restrict__ Bw,
                  const float* __restrict__ bias, const float* __restrict__ res,
                  float* __restrict__ C, int N, int K) {
    const int BM = 128, BN = 64, BK = 16, TM = 8, TN = 4;
    __shared__ float As[BK][BM];
    __shared__ float Bs[BK][BN];

    int tid = threadIdx.x;
    int tx = tid & 15;        // 16 col-groups
    int ty = tid >> 4;        // 16 row-groups
    int blockRow = blockIdx.x * BM;
    int blockCol = blockIdx.y * BN;

    float acc[TM][TN];
#pragma unroll
    for (int i = 0; i < TM; i++)
#pragma unroll
        for (int j = 0; j < TN; j++) acc[i][j] = 0.f;

    int arow0 = tid >> 2;     // 0..63, +64 for second row
    int acol4 = tid & 3;      // which float4 of the 16-wide k slab
    int brow  = tid >> 4;     // 0..15
    int bcol4 = tid & 15;     // 0..15

    for (int k0 = 0; k0 < K; k0 += BK) {
#pragma unroll
        for (int r = 0; r < 2; r++) {
            int row = arow0 + r * 64;
            float4 a = *(const float4*)(A + (size_t)(blockRow + row) * K + k0 + acol4 * 4);
            As[acol4*4+0][row] = a.x; As[acol4*4+1][row] = a.y;
            As[acol4*4+2][row] = a.z; As[acol4*4+3][row] = a.w;
        }
        *(float4*)&Bs[brow][bcol4 * 4] =
            *(const float4*)(Bw + (size_t)(k0 + brow) * N + blockCol + bcol4 * 4);
        __syncthreads();

#pragma unroll
        for (int kk = 0; kk < BK; kk++) {
            float4 ra0 = *(const float4*)&As[kk][ty * TM];
            float4 ra1 = *(const float4*)&As[kk][ty * TM + 4];
            float4 rb  = *(const float4*)&Bs[kk][tx * TN];
            float ra[TM] = {ra0.x, ra0.y, ra0.z, ra0.w, ra1.x, ra1.y, ra1.z, ra1.w};
            float rbv[TN] = {rb.x, rb.y, rb.z, rb.w};
#pragma unroll
            for (int i = 0; i < TM; i++)
#pragma unroll
                for (int j = 0; j < TN; j++) acc[i][j] += ra[i] * rbv[j];
        }
        __syncthreads();
    }

#pragma unroll
    for (int i = 0; i < TM; i++) {
        int row = blockRow + ty * TM + i;
        int drow = (EPI == 1) ? winrow_to_xrow(row) : row;
#pragma unroll
        for (int j = 0; j < TN; j++) {
            int col = blockCol + tx * TN + j;
            float val = acc[i][j] + bias[col];
            if (EPI == 2) {
                val = 0.5f * val * (1.f + erff(val * 0.70710678118654752f));
            }
            if (EPI == 3) {
                val += res[(size_t)row * N + col];
            }
            C[(size_t)drow * N + col] = val;
        }
    }
}

// ---------------- launch ----------------------------------------------------
extern "C" void kernel_launch(void* const* d_in, const int* in_sizes, int n_in,
                              void* d_out, int out_size) {
    const float* x      = (const float*)d_in[0];
    const float* qkv_w  = (const float*)d_in[1];
    const float* qkv_b  = (const float*)d_in[2];
    const float* proj_w = (const float*)d_in[3];
    const float* proj_b = (const float*)d_in[4];
    const float* g1     = (const float*)d_in[5];
    const float* be1    = (const float*)d_in[6];
    const float* g2     = (const float*)d_in[7];
    const float* be2    = (const float*)d_in[8];
    const float* w1     = (const float*)d_in[9];
    const float* b1     = (const float*)d_in[10];
    const float* w2     = (const float*)d_in[11];
    const float* b2     = (const float*)d_in[12];
    float* out = (float*)d_out;

    float *xn, *qkv, *attn, *xbuf, *hid;
    cudaGetSymbolAddress((void**)&xn,   g_xn);
    cudaGetSymbolAddress((void**)&qkv,  g_qkv);
    cudaGetSymbolAddress((void**)&attn, g_attn);
    cudaGetSymbolAddress((void**)&xbuf, g_x);
    cudaGetSymbolAddress((void**)&hid,  g_hid);

    const int MT = MROWS / 128;   // 784 M-tiles

    // 1) gather (cyclic shift + window partition) + LN1 -> xn (window order)
    ln_kernel<true><<<MROWS / 8, 256>>>(x, g1, be1, xn);
    // 2) QKV GEMM: [M,192] @ [192,576] + b -> qkv (window order)
    sgemm_kernel<0><<<dim3(MT, 576 / 64), 256>>>(xn, qkv_w, qkv_b, nullptr, qkv, 576, DIMC);
    // 3) windowed attention per (window, head)
    attn_kernel<<<dim3(NWIN, NHEAD), 128>>>(qkv, attn);
    // 4) proj GEMM + scatter (window reverse + roll back) -> xbuf (x order)
    sgemm_kernel<1><<<dim3(MT, 192 / 64), 256>>>(attn, proj_w, proj_b, nullptr, xbuf, DIMC, DIMC);
    // 5) LN2 -> xn (x order, reuse buffer)
    ln_kernel<false><<<MROWS / 8, 256>>>(xbuf, g2, be2, xn);
    // 6) FC1 + exact GELU -> hid
    sgemm_kernel<2><<<dim3(MT, HIDDEN / 64), 256>>>(xn, w1, b1, nullptr, hid, HIDDEN, DIMC);
    // 7) FC2 + residual(xbuf) -> out
    sgemm_kernel<3><<<dim3(MT, 192 / 64), 256>>>(hid, w2, b2, xbuf, out, DIMC, HIDDEN);
}

// round 3
// speedup vs baseline: 1.4907x; 1.4907x over previous
#include <cuda_runtime.h>
#include <math.h>
#include <stdint.h>

#define BATCH 32
#define HW    56
#define DIMC  192
#define LTOK  (HW*HW)
#define MROWS (BATCH*LTOK)       /* 100352 */
#define NHEAD 6
#define HD    32
#define NWIN  2048
#define HIDDEN 768
#define SS    3

// ---------------- scratch ----------------
__device__ float g_xn   [(size_t)MROWS * DIMC];
__device__ float g_qkv  [(size_t)MROWS * 3 * DIMC];
__device__ float g_attn [(size_t)MROWS * DIMC];
__device__ float g_x    [(size_t)MROWS * DIMC];
__device__ float g_hid  [(size_t)MROWS * HIDDEN];

__device__ __forceinline__ int winrow_to_xrow(int r) {
    int win = r / 49, n = r % 49;
    int bb = win >> 6;
    int wrem = win & 63;
    int wh = wrem >> 3, ww = wrem & 7;
    int i = n / 7, j = n % 7;
    int h = wh * 7 + i + SS; if (h >= HW) h -= HW;
    int w = ww * 7 + j + SS; if (w >= HW) w -= HW;
    return bb * LTOK + h * HW + w;
}

__device__ __forceinline__ uint32_t cvt_tf32(float x) {
    uint32_t r; asm("cvt.rna.tf32.f32 %0, %1;" : "=r"(r) : "f"(x)); return r;
}

// ---------------- LayerNorm ----------------
template<bool GATHER>
__global__ void ln_kernel(const float* __restrict__ x,
                          const float* __restrict__ g,
                          const float* __restrict__ b,
                          float* __restrict__ out) {
    int row  = blockIdx.x * 8 + (threadIdx.x >> 5);
    int lane = threadIdx.x & 31;
    int srow = GATHER ? winrow_to_xrow(row) : row;
    const float* src = x + (size_t)srow * DIMC;

    float v[6];
    float sum = 0.f;
#pragma unroll
    for (int t = 0; t < 6; t++) { v[t] = src[lane + 32 * t]; sum += v[t]; }
#pragma unroll
    for (int o = 16; o > 0; o >>= 1) sum += __shfl_xor_sync(0xffffffffu, sum, o);
    float mu = sum * (1.f / DIMC);
    float vs = 0.f;
#pragma unroll
    for (int t = 0; t < 6; t++) { float d = v[t] - mu; vs += d * d; }
#pragma unroll
    for (int o = 16; o > 0; o >>= 1) vs += __shfl_xor_sync(0xffffffffu, vs, o);
    float inv = rsqrtf(vs * (1.f / DIMC) + 1e-5f);

    float* dst = out + (size_t)row * DIMC;
#pragma unroll
    for (int t = 0; t < 6; t++) {
        int c = lane + 32 * t;
        dst[c] = (v[t] - mu) * inv * g[c] + b[c];
    }
}

// ---------------- attention ----------------
__global__ void attn_kernel(const float* __restrict__ qkv, float* __restrict__ out) {
    int win = blockIdx.x, head = blockIdx.y;
    int tid = threadIdx.x;

    __shared__ float sq[49][33], sk[49][33], sv[49][33];
    __shared__ float ss[49][49];

    const float* base = qkv + (size_t)win * 49 * (3 * DIMC) + head * HD;
    for (int idx = tid; idx < 49 * 8; idx += blockDim.x) {
        int n = idx >> 3, d4 = idx & 7;
        const float* row = base + (size_t)n * (3 * DIMC);
        float4 q4 = *(const float4*)(row + d4 * 4);
        float4 k4 = *(const float4*)(row + DIMC + d4 * 4);
        float4 v4 = *(const float4*)(row + 2 * DIMC + d4 * 4);
        sq[n][d4*4+0]=q4.x; sq[n][d4*4+1]=q4.y; sq[n][d4*4+2]=q4.z; sq[n][d4*4+3]=q4.w;
        sk[n][d4*4+0]=k4.x; sk[n][d4*4+1]=k4.y; sk[n][d4*4+2]=k4.z; sk[n][d4*4+3]=k4.w;
        sv[n][d4*4+0]=v4.x; sv[n][d4*4+1]=v4.y; sv[n][d4*4+2]=v4.z; sv[n][d4*4+3]=v4.w;
    }
    __syncthreads();

    const float scale = 0.17677669529663687f;
    for (int idx = tid; idx < 49 * 49; idx += blockDim.x) {
        int n = idx / 49, m = idx % 49;
        float acc = 0.f;
#pragma unroll
        for (int d = 0; d < HD; d++) acc += sq[n][d] * sk[m][d];
        ss[n][m] = acc * scale;
    }
    __syncthreads();

    if (tid < 49) {
        float mx = -1e30f;
#pragma unroll 7
        for (int m = 0; m < 49; m++) mx = fmaxf(mx, ss[tid][m]);
        float sum = 0.f;
#pragma unroll 7
        for (int m = 0; m < 49; m++) { float e = __expf(ss[tid][m] - mx); ss[tid][m] = e; sum += e; }
        float inv = 1.f / sum;
#pragma unroll 7
        for (int m = 0; m < 49; m++) ss[tid][m] *= inv;
    }
    __syncthreads();

    float* obase = out + (size_t)win * 49 * DIMC + head * HD;
    for (int idx = tid; idx < 49 * HD; idx += blockDim.x) {
        int n = idx >> 5, d = idx & 31;
        float acc = 0.f;
#pragma unroll 7
        for (int m = 0; m < 49; m++) acc += ss[n][m] * sv[m][d];
        obase[(size_t)n * DIMC + d] = acc;
    }
}

// ---------------- tf32 mma.sync GEMM ----------------
// C[M,N] = A[M,K] @ B[K,N] + epilogue. K = KCH*192.
// A chunk (128 x 192) resident in smem, read from DRAM once per k-chunk.
// Inner loop over NT tiles of 64 cols; B streamed via 64x48 smem buffer.
// 256 threads = 8 warps (4 m x 2 n), warp tile 32x32 (mi 2 x ni 4 of m16n8k8).
// EPI: 0 bias; 1 bias+scatter; 2 bias+gelu; 3 bias+residual
#define A_STRIDE 196
#define B_STRIDE 52
#define GEMM_SMEM ((128*A_STRIDE + 64*B_STRIDE) * 4)

template<int EPI, int NT, int KCH>
__global__ __launch_bounds__(256)
void mmagemm(const float* __restrict__ A, const float* __restrict__ Bw,
             const float* __restrict__ bias, const float* __restrict__ res,
             float* __restrict__ C) {
    constexpr int K = KCH * 192;
    constexpr int N = NT * 64;
    constexpr int HOLD = (KCH > 1) ? NT : 1;

    extern __shared__ float sm[];
    float* As = sm;                      // [128][A_STRIDE]
    float* Bs = sm + 128 * A_STRIDE;     // [64][B_STRIDE]

    int tid = threadIdx.x, lane = tid & 31, wid = tid >> 5;
    int warpm = (wid & 3) * 32;
    int warpn = (wid >> 2) * 32;
    int row0 = blockIdx.x * 128;

    float acc[HOLD][2][4][4];
#pragma unroll
    for (int h = 0; h < HOLD; h++)
#pragma unroll
        for (int mi = 0; mi < 2; mi++)
#pragma unroll
            for (int ni = 0; ni < 4; ni++)
#pragma unroll
                for (int c = 0; c < 4; c++) acc[h][mi][ni][c] = 0.f;

    for (int kc = 0; kc < KCH; kc++) {
        __syncthreads();
        // ---- load A chunk 128 x 192 (cvt to tf32) ----
#pragma unroll
        for (int i = 0; i < 24; i++) {
            int idx = tid + i * 256;
            int row = idx / 48, k4 = (idx % 48) * 4;
            float4 a = *(const float4*)(A + (size_t)(row0 + row) * K + kc * 192 + k4);
            uint4 w = make_uint4(cvt_tf32(a.x), cvt_tf32(a.y), cvt_tf32(a.z), cvt_tf32(a.w));
            *(uint4*)(As + row * A_STRIDE + k4) = w;
        }

#pragma unroll 1
        for (int nt = 0; nt < NT; nt++) {
            const int h = (KCH > 1) ? nt : 0;
#pragma unroll
            for (int kb = 0; kb < 4; kb++) {
                __syncthreads();
                // ---- load B sub-chunk: 48 k-rows x 64 cols ----
#pragma unroll
                for (int i = 0; i < 3; i++) {
                    int idx = tid + i * 256;
                    int k = idx / 16, n4 = (idx % 16) * 4;
                    float4 b = *(const float4*)(Bw + (size_t)(kc * 192 + kb * 48 + k) * N + nt * 64 + n4);
                    Bs[(n4 + 0) * B_STRIDE + k] = __uint_as_float(cvt_tf32(b.x));
                    Bs[(n4 + 1) * B_STRIDE + k] = __uint_as_float(cvt_tf32(b.y));
                    Bs[(n4 + 2) * B_STRIDE + k] = __uint_as_float(cvt_tf32(b.z));
                    Bs[(n4 + 3) * B_STRIDE + k] = __uint_as_float(cvt_tf32(b.w));
                }
                __syncthreads();
#pragma unroll
                for (int ks = 0; ks < 6; ks++) {
                    int kk = kb * 48 + ks * 8;       // A-local k
                    int bk = ks * 8;                  // B-local k
                    uint32_t af[2][4];
#pragma unroll
                    for (int mi = 0; mi < 2; mi++) {
                        int r = warpm + mi * 16 + (lane >> 2);
                        int kc0 = kk + (lane & 3);
                        af[mi][0] = __float_as_uint(As[r * A_STRIDE + kc0]);
                        af[mi][1] = __float_as_uint(As[(r + 8) * A_STRIDE + kc0]);
                        af[mi][2] = __float_as_uint(As[r * A_STRIDE + kc0 + 4]);
                        af[mi][3] = __float_as_uint(As[(r + 8) * A_STRIDE + kc0 + 4]);
                    }
                    uint32_t bf[4][2];
#pragma unroll
                    for (int ni = 0; ni < 4; ni++) {
                        int col = warpn + ni * 8 + (lane >> 2);
                        int kr = kb * 0 + bk + (lane & 3);
                        bf[ni][0] = __float_as_uint(Bs[col * B_STRIDE + kr]);
                        bf[ni][1] = __float_as_uint(Bs[col * B_STRIDE + kr + 4]);
                    }
#pragma unroll
                    for (int mi = 0; mi < 2; mi++)
#pragma unroll
                        for (int ni = 0; ni < 4; ni++) {
                            float* c = acc[h][mi][ni];
                            asm volatile(
                                "mma.sync.aligned.m16n8k8.row.col.f32.tf32.tf32.f32 "
                                "{%0,%1,%2,%3}, {%4,%5,%6,%7}, {%8,%9}, {%0,%1,%2,%3};"
                                : "+f"(c[0]), "+f"(c[1]), "+f"(c[2]), "+f"(c[3])
                                : "r"(af[mi][0]), "r"(af[mi][1]), "r"(af[mi][2]), "r"(af[mi][3]),
                                  "r"(bf[ni][0]), "r"(bf[ni][1]));
                        }
                }
            }
            if (KCH == 1) {
                // epilogue for this n-tile, then reset acc
#pragma unroll
                for (int mi = 0; mi < 2; mi++)
#pragma unroll
                    for (int ni = 0; ni < 4; ni++) {
#pragma unroll
                        for (int half = 0; half < 2; half++) {
                            int r = row0 + warpm + mi * 16 + (lane >> 2) + half * 8;
                            int cgl = nt * 64 + warpn + ni * 8 + 2 * (lane & 3);
                            float v0 = acc[0][mi][ni][half * 2 + 0] + bias[cgl];
                            float v1 = acc[0][mi][ni][half * 2 + 1] + bias[cgl + 1];
                            if (EPI == 2) {
                                v0 = 0.5f * v0 * (1.f + erff(v0 * 0.70710678118654752f));
                                v1 = 0.5f * v1 * (1.f + erff(v1 * 0.70710678118654752f));
                            }
                            if (EPI == 3) {
                                v0 += res[(size_t)r * N + cgl];
                                v1 += res[(size_t)r * N + cgl + 1];
                            }
                            int dr = (EPI == 1) ? winrow_to_xrow(r) : r;
                            *(float2*)(C + (size_t)dr * N + cgl) = make_float2(v0, v1);
                        }
#pragma unroll
                        for (int c = 0; c < 4; c++) acc[0][mi][ni][c] = 0.f;
                    }
            }
        }
    }

    if (KCH > 1) {
#pragma unroll
        for (int nt = 0; nt < NT; nt++)
#pragma unroll
            for (int mi = 0; mi < 2; mi++)
#pragma unroll
                for (int ni = 0; ni < 4; ni++)
#pragma unroll
                    for (int half = 0; half < 2; half++) {
                        int r = row0 + warpm + mi * 16 + (lane >> 2) + half * 8;
                        int cgl = nt * 64 + warpn + ni * 8 + 2 * (lane & 3);
                        float v0 = acc[nt][mi][ni][half * 2 + 0] + bias[cgl];
                        float v1 = acc[nt][mi][ni][half * 2 + 1] + bias[cgl + 1];
                        if (EPI == 2) {
                            v0 = 0.5f * v0 * (1.f + erff(v0 * 0.70710678118654752f));
                            v1 = 0.5f * v1 * (1.f + erff(v1 * 0.70710678118654752f));
                        }
                        if (EPI == 3) {
                            v0 += res[(size_t)r * N + cgl];
                            v1 += res[(size_t)r * N + cgl + 1];
                        }
                        int dr = (EPI == 1) ? winrow_to_xrow(r) : r;
                        *(float2*)(C + (size_t)dr * N + cgl) = make_float2(v0, v1);
                    }
    }
}

// ---------------- launch ----------------
extern "C" void kernel_launch(void* const* d_in, const int* in_sizes, int n_in,
                              void* d_out, int out_size) {
    const float* x      = (const float*)d_in[0];
    const float* qkv_w  = (const float*)d_in[1];
    const float* qkv_b  = (const float*)d_in[2];
    const float* proj_w = (const float*)d_in[3];
    const float* proj_b = (const float*)d_in[4];
    const float* g1     = (const float*)d_in[5];
    const float* be1    = (const float*)d_in[6];
    const float* g2     = (const float*)d_in[7];
    const float* be2    = (const float*)d_in[8];
    const float* w1     = (const float*)d_in[9];
    const float* b1     = (const float*)d_in[10];
    const float* w2     = (const float*)d_in[11];
    const float* b2     = (const float*)d_in[12];
    float* out = (float*)d_out;

    float *xn, *qkv, *attn, *xbuf, *hid;
    cudaGetSymbolAddress((void**)&xn,   g_xn);
    cudaGetSymbolAddress((void**)&qkv,  g_qkv);
    cudaGetSymbolAddress((void**)&attn, g_attn);
    cudaGetSymbolAddress((void**)&xbuf, g_x);
    cudaGetSymbolAddress((void**)&hid,  g_hid);

    cudaFuncSetAttribute(mmagemm<0, 9, 1>,  cudaFuncAttributeMaxDynamicSharedMemorySize, GEMM_SMEM);
    cudaFuncSetAttribute(mmagemm<1, 3, 1>,  cudaFuncAttributeMaxDynamicSharedMemorySize, GEMM_SMEM);
    cudaFuncSetAttribute(mmagemm<2, 12, 1>, cudaFuncAttributeMaxDynamicSharedMemorySize, GEMM_SMEM);
    cudaFuncSetAttribute(mmagemm<3, 3, 4>,  cudaFuncAttributeMaxDynamicSharedMemorySize, GEMM_SMEM);

    const int MT = MROWS / 128;   // 784

    // 1) shift-gather + LN1
    ln_kernel<true><<<MROWS / 8, 256>>>(x, g1, be1, xn);
    // 2) QKV GEMM [M,192]x[192,576]
    mmagemm<0, 9, 1><<<MT, 256, GEMM_SMEM>>>(xn, qkv_w, qkv_b, nullptr, qkv);
    // 3) windowed attention
    attn_kernel<<<dim3(NWIN, NHEAD), 128>>>(qkv, attn);
    // 4) proj GEMM + reverse-shift scatter
    mmagemm<1, 3, 1><<<MT, 256, GEMM_SMEM>>>(attn, proj_w, proj_b, nullptr, xbuf);
    // 5) LN2
    ln_kernel<false><<<MROWS / 8, 256>>>(xbuf, g2, be2, xn);
    // 6) FC1 + GELU
    mmagemm<2, 12, 1><<<MT, 256, GEMM_SMEM>>>(xn, w1, b1, nullptr, hid);
    // 7) FC2 + residual
    mmagemm<3, 3, 4><<<MT, 256, GEMM_SMEM>>>(hid, w2, b2, xbuf, out);
}

// round 4
// speedup vs baseline: 1.9971x; 1.3398x over previous
#include <cuda_runtime.h>
#include <math.h>
#include <stdint.h>

#define BATCH 32
#define HW    56
#define DIMC  192
#define LTOK  (HW*HW)
#define MROWS (BATCH*LTOK)       /* 100352 */
#define NHEAD 6
#define HD    32
#define NWIN  2048
#define HIDDEN 768
#define SS    3

// ---------------- scratch ----------------
__device__ float g_xn   [(size_t)MROWS * DIMC];
__device__ float g_qkv  [(size_t)MROWS * 3 * DIMC];
__device__ float g_attn [(size_t)MROWS * DIMC];
__device__ float g_x    [(size_t)MROWS * DIMC];
__device__ float g_hid  [(size_t)MROWS * HIDDEN];

__device__ __forceinline__ int winrow_to_xrow(int r) {
    int win = r / 49, n = r % 49;
    int bb = win >> 6;
    int wrem = win & 63;
    int wh = wrem >> 3, ww = wrem & 7;
    int i = n / 7, j = n % 7;
    int h = wh * 7 + i + SS; if (h >= HW) h -= HW;
    int w = ww * 7 + j + SS; if (w >= HW) w -= HW;
    return bb * LTOK + h * HW + w;
}

__device__ __forceinline__ uint32_t cvt_tf32(float x) {
    uint32_t r; asm("cvt.rna.tf32.f32 %0, %1;" : "=r"(r) : "f"(x)); return r;
}
__device__ __forceinline__ uint4 cvt4(float4 v) {
    return make_uint4(cvt_tf32(v.x), cvt_tf32(v.y), cvt_tf32(v.z), cvt_tf32(v.w));
}

// ---------------- LayerNorm ----------------
template<bool GATHER>
__global__ void ln_kernel(const float* __restrict__ x,
                          const float* __restrict__ g,
                          const float* __restrict__ b,
                          float* __restrict__ out) {
    int row  = blockIdx.x * 8 + (threadIdx.x >> 5);
    int lane = threadIdx.x & 31;
    int srow = GATHER ? winrow_to_xrow(row) : row;
    const float* src = x + (size_t)srow * DIMC;

    float v[6];
    float sum = 0.f;
#pragma unroll
    for (int t = 0; t < 6; t++) { v[t] = src[lane + 32 * t]; sum += v[t]; }
#pragma unroll
    for (int o = 16; o > 0; o >>= 1) sum += __shfl_xor_sync(0xffffffffu, sum, o);
    float mu = sum * (1.f / DIMC);
    float vs = 0.f;
#pragma unroll
    for (int t = 0; t < 6; t++) { float d = v[t] - mu; vs += d * d; }
#pragma unroll
    for (int o = 16; o > 0; o >>= 1) vs += __shfl_xor_sync(0xffffffffu, vs, o);
    float inv = rsqrtf(vs * (1.f / DIMC) + 1e-5f);

    float* dst = out + (size_t)row * DIMC;
#pragma unroll
    for (int t = 0; t < 6; t++) {
        int c = lane + 32 * t;
        dst[c] = (v[t] - mu) * inv * g[c] + b[c];
    }
}

// ---------------- attention ----------------
__global__ void attn_kernel(const float* __restrict__ qkv, float* __restrict__ out) {
    int win = blockIdx.x, head = blockIdx.y;
    int tid = threadIdx.x;

    __shared__ float sq[49][33], sk[49][33], sv[49][33];
    __shared__ float ss[49][49];

    const float* base = qkv + (size_t)win * 49 * (3 * DIMC) + head * HD;
    for (int idx = tid; idx < 49 * 8; idx += blockDim.x) {
        int n = idx >> 3, d4 = idx & 7;
        const float* row = base + (size_t)n * (3 * DIMC);
        float4 q4 = *(const float4*)(row + d4 * 4);
        float4 k4 = *(const float4*)(row + DIMC + d4 * 4);
        float4 v4 = *(const float4*)(row + 2 * DIMC + d4 * 4);
        sq[n][d4*4+0]=q4.x; sq[n][d4*4+1]=q4.y; sq[n][d4*4+2]=q4.z; sq[n][d4*4+3]=q4.w;
        sk[n][d4*4+0]=k4.x; sk[n][d4*4+1]=k4.y; sk[n][d4*4+2]=k4.z; sk[n][d4*4+3]=k4.w;
        sv[n][d4*4+0]=v4.x; sv[n][d4*4+1]=v4.y; sv[n][d4*4+2]=v4.z; sv[n][d4*4+3]=v4.w;
    }
    __syncthreads();

    const float scale = 0.17677669529663687f;
    for (int idx = tid; idx < 49 * 49; idx += blockDim.x) {
        int n = idx / 49, m = idx % 49;
        float acc = 0.f;
#pragma unroll
        for (int d = 0; d < HD; d++) acc += sq[n][d] * sk[m][d];
        ss[n][m] = acc * scale;
    }
    __syncthreads();

    if (tid < 49) {
        float mx = -1e30f;
#pragma unroll 7
        for (int m = 0; m < 49; m++) mx = fmaxf(mx, ss[tid][m]);
        float sum = 0.f;
#pragma unroll 7
        for (int m = 0; m < 49; m++) { float e = __expf(ss[tid][m] - mx); ss[tid][m] = e; sum += e; }
        float inv = 1.f / sum;
#pragma unroll 7
        for (int m = 0; m < 49; m++) ss[tid][m] *= inv;
    }
    __syncthreads();

    float* obase = out + (size_t)win * 49 * DIMC + head * HD;
    for (int idx = tid; idx < 49 * HD; idx += blockDim.x) {
        int n = idx >> 5, d = idx & 31;
        float acc = 0.f;
#pragma unroll 7
        for (int m = 0; m < 49; m++) acc += ss[n][m] * sv[m][d];
        obase[(size_t)n * DIMC + d] = acc;
    }
}

// ---------------- tf32 mma.sync GEMM, double-buffered ----------------
// C[M,N] = A[M,K] @ B[K,N] + epilogue. BM=128, BN=64, BK=32.
// 128 threads = 4 warps (2m x 2n), warp tile 64x32 (mi4 x ni4 m16n8k8).
// smem: A [m][k] stride 36, B [k][n] stride 72, both double-buffered (55 KB).
// EPI: 0 bias; 1 bias+scatter; 2 bias+gelu; 3 bias+residual
#define AS_W 4608   /* 128*36 words per buffer */
#define BS_W 2304   /* 32*72 words per buffer */
#define GEMM_SMEM ((2*AS_W + 2*BS_W) * 4)

template<int EPI, int N, int K>
__global__ __launch_bounds__(128)
void mmagemm(const float* __restrict__ A, const float* __restrict__ Bw,
             const float* __restrict__ bias, const float* __restrict__ res,
             float* __restrict__ C) {
    constexpr int KT = K / 32;

    extern __shared__ float sm[];
    int tid = threadIdx.x, lane = tid & 31, wid = tid >> 5;
    int warpm = (wid & 1) * 64;
    int warpn = (wid >> 1) * 32;
    int row0 = blockIdx.y * 128;
    int col0 = blockIdx.x * 64;

    float acc[4][4][4];
#pragma unroll
    for (int mi = 0; mi < 4; mi++)
#pragma unroll
        for (int ni = 0; ni < 4; ni++)
#pragma unroll
            for (int c = 0; c < 4; c++) acc[mi][ni][c] = 0.f;

    float4 pa[8], pb[4];

    // thread-fixed load coordinates
    const int a_row = tid >> 3;            // +16 per i
    const int a_kq  = (tid & 7) * 4;
    const int b_k   = tid >> 4;            // +8 per i
    const int b_nq  = (tid & 15) * 4;

    // prefetch kt=0
#pragma unroll
    for (int i = 0; i < 8; i++)
        pa[i] = *(const float4*)(A + (size_t)(row0 + a_row + i * 16) * K + a_kq);
#pragma unroll
    for (int i = 0; i < 4; i++)
        pb[i] = *(const float4*)(Bw + (size_t)(b_k + i * 8) * N + col0 + b_nq);
    {
        float* as = sm; float* bs = sm + 2 * AS_W;
#pragma unroll
        for (int i = 0; i < 8; i++)
            *(uint4*)(as + (a_row + i * 16) * 36 + a_kq) = cvt4(pa[i]);
#pragma unroll
        for (int i = 0; i < 4; i++)
            *(uint4*)(bs + (b_k + i * 8) * 72 + b_nq) = cvt4(pb[i]);
    }
    __syncthreads();

#pragma unroll 1
    for (int kt = 0; kt < KT; kt++) {
        int cur = kt & 1;
        if (kt + 1 < KT) {
#pragma unroll
            for (int i = 0; i < 8; i++)
                pa[i] = *(const float4*)(A + (size_t)(row0 + a_row + i * 16) * K + (kt + 1) * 32 + a_kq);
#pragma unroll
            for (int i = 0; i < 4; i++)
                pb[i] = *(const float4*)(Bw + (size_t)((kt + 1) * 32 + b_k + i * 8) * N + col0 + b_nq);
        }

        const float* as = sm + cur * AS_W;
        const float* bs = sm + 2 * AS_W + cur * BS_W;
#pragma unroll
        for (int ks = 0; ks < 4; ks++) {
            int kk = ks * 8 + (lane & 3);
            uint32_t af[4][4], bf[4][2];
#pragma unroll
            for (int mi = 0; mi < 4; mi++) {
                int r = warpm + mi * 16 + (lane >> 2);
                af[mi][0] = __float_as_uint(as[r * 36 + kk]);
                af[mi][1] = __float_as_uint(as[(r + 8) * 36 + kk]);
                af[mi][2] = __float_as_uint(as[r * 36 + kk + 4]);
                af[mi][3] = __float_as_uint(as[(r + 8) * 36 + kk + 4]);
            }
#pragma unroll
            for (int ni = 0; ni < 4; ni++) {
                int n = warpn + ni * 8 + (lane >> 2);
                bf[ni][0] = __float_as_uint(bs[kk * 72 + n]);
                bf[ni][1] = __float_as_uint(bs[(kk + 4) * 72 + n]);
            }
#pragma unroll
            for (int mi = 0; mi < 4; mi++)
#pragma unroll
                for (int ni = 0; ni < 4; ni++) {
                    float* c = acc[mi][ni];
                    asm volatile(
                        "mma.sync.aligned.m16n8k8.row.col.f32.tf32.tf32.f32 "
                        "{%0,%1,%2,%3}, {%4,%5,%6,%7}, {%8,%9}, {%0,%1,%2,%3};"
                        : "+f"(c[0]), "+f"(c[1]), "+f"(c[2]), "+f"(c[3])
                        : "r"(af[mi][0]), "r"(af[mi][1]), "r"(af[mi][2]), "r"(af[mi][3]),
                          "r"(bf[ni][0]), "r"(bf[ni][1]));
                }
        }

        if (kt + 1 < KT) {
            int nxt = cur ^ 1;
            float* asw = sm + nxt * AS_W;
            float* bsw = sm + 2 * AS_W + nxt * BS_W;
#pragma unroll
            for (int i = 0; i < 8; i++)
                *(uint4*)(asw + (a_row + i * 16) * 36 + a_kq) = cvt4(pa[i]);
#pragma unroll
            for (int i = 0; i < 4; i++)
                *(uint4*)(bsw + (b_k + i * 8) * 72 + b_nq) = cvt4(pb[i]);
            __syncthreads();
        }
    }

    // ---- epilogue ----
#pragma unroll
    for (int mi = 0; mi < 4; mi++)
#pragma unroll
        for (int ni = 0; ni < 4; ni++)
#pragma unroll
            for (int half = 0; half < 2; half++) {
                int r = row0 + warpm + mi * 16 + (lane >> 2) + half * 8;
                int cg = col0 + warpn + ni * 8 + 2 * (lane & 3);
                float v0 = acc[mi][ni][half * 2 + 0] + bias[cg];
                float v1 = acc[mi][ni][half * 2 + 1] + bias[cg + 1];
                if (EPI == 2) {
                    v0 = 0.5f * v0 * (1.f + erff(v0 * 0.70710678118654752f));
                    v1 = 0.5f * v1 * (1.f + erff(v1 * 0.70710678118654752f));
                }
                if (EPI == 3) {
                    v0 += res[(size_t)r * N + cg];
                    v1 += res[(size_t)r * N + cg + 1];
                }
                int dr = (EPI == 1) ? winrow_to_xrow(r) : r;
                *(float2*)(C + (size_t)dr * N + cg) = make_float2(v0, v1);
            }
}

// ---------------- launch ----------------
extern "C" void kernel_launch(void* const* d_in, const int* in_sizes, int n_in,
                              void* d_out, int out_size) {
    const float* x      = (const float*)d_in[0];
    const float* qkv_w  = (const float*)d_in[1];
    const float* qkv_b  = (const float*)d_in[2];
    const float* proj_w = (const float*)d_in[3];
    const float* proj_b = (const float*)d_in[4];
    const float* g1     = (const float*)d_in[5];
    const float* be1    = (const float*)d_in[6];
    const float* g2     = (const float*)d_in[7];
    const float* be2    = (const float*)d_in[8];
    const float* w1     = (const float*)d_in[9];
    const float* b1     = (const float*)d_in[10];
    const float* w2     = (const float*)d_in[11];
    const float* b2     = (const float*)d_in[12];
    float* out = (float*)d_out;

    float *xn, *qkv, *attn, *xbuf, *hid;
    cudaGetSymbolAddress((void**)&xn,   g_xn);
    cudaGetSymbolAddress((void**)&qkv,  g_qkv);
    cudaGetSymbolAddress((void**)&attn, g_attn);
    cudaGetSymbolAddress((void**)&xbuf, g_x);
    cudaGetSymbolAddress((void**)&hid,  g_hid);

    cudaFuncSetAttribute(mmagemm<0, 576, 192>, cudaFuncAttributeMaxDynamicSharedMemorySize, GEMM_SMEM);
    cudaFuncSetAttribute(mmagemm<1, 192, 192>, cudaFuncAttributeMaxDynamicSharedMemorySize, GEMM_SMEM);
    cudaFuncSetAttribute(mmagemm<2, 768, 192>, cudaFuncAttributeMaxDynamicSharedMemorySize, GEMM_SMEM);
    cudaFuncSetAttribute(mmagemm<3, 192, 768>, cudaFuncAttributeMaxDynamicSharedMemorySize, GEMM_SMEM);

    const int MT = MROWS / 128;   // 784

    // 1) shift-gather + LN1
    ln_kernel<true><<<MROWS / 8, 256>>>(x, g1, be1, xn);
    // 2) QKV GEMM [M,192]x[192,576]
    mmagemm<0, 576, 192><<<dim3(9, MT), 128, GEMM_SMEM>>>(xn, qkv_w, qkv_b, nullptr, qkv);
    // 3) windowed attention
    attn_kernel<<<dim3(NWIN, NHEAD), 128>>>(qkv, attn);
    // 4) proj GEMM + reverse-shift scatter
    mmagemm<1, 192, 192><<<dim3(3, MT), 128, GEMM_SMEM>>>(attn, proj_w, proj_b, nullptr, xbuf);
    // 5) LN2
    ln_kernel<false><<<MROWS / 8, 256>>>(xbuf, g2, be2, xn);
    // 6) FC1 + GELU
    mmagemm<2, 768, 192><<<dim3(12, MT), 128, GEMM_SMEM>>>(xn, w1, b1, nullptr, hid);
    // 7) FC2 + residual
    mmagemm<3, 192, 768><<<dim3(3, MT), 128, GEMM_SMEM>>>(hid, w2, b2, xbuf, out);
}

// round 5
// speedup vs baseline: 2.2104x; 1.1068x over previous
#include <cuda_runtime.h>
#include <math.h>
#include <stdint.h>

#define BATCH 32
#define HW    56
#define DIMC  192
#define LTOK  (HW*HW)
#define MROWS (BATCH*LTOK)       /* 100352 */
#define NHEAD 6
#define HD    32
#define NWIN  2048
#define HIDDEN 768
#define SS    3

// ---------------- scratch ----------------
__device__ float g_xn   [(size_t)MROWS * DIMC];
__device__ float g_qkv  [(size_t)MROWS * 3 * DIMC];
__device__ float g_attn [(size_t)MROWS * DIMC];
__device__ float g_x    [(size_t)MROWS * DIMC];
__device__ float g_hid  [(size_t)MROWS * HIDDEN];
__device__ float g_w    [DIMC*3*DIMC + DIMC*DIMC + DIMC*HIDDEN + HIDDEN*DIMC]; // rounded weights

__device__ __forceinline__ int winrow_to_xrow(int r) {
    int win = r / 49, n = r % 49;
    int bb = win >> 6;
    int wrem = win & 63;
    int wh = wrem >> 3, ww = wrem & 7;
    int i = n / 7, j = n % 7;
    int h = wh * 7 + i + SS; if (h >= HW) h -= HW;
    int w = ww * 7 + j + SS; if (w >= HW) w -= HW;
    return bb * LTOK + h * HW + w;
}

__device__ __forceinline__ uint32_t cvt_tf32(float x) {
    uint32_t r; asm("cvt.rna.tf32.f32 %0, %1;" : "=r"(r) : "f"(x)); return r;
}
__device__ __forceinline__ float rnd_tf32(float x) { return __uint_as_float(cvt_tf32(x)); }

__device__ __forceinline__ uint32_t smem_u32(const void* p) {
    uint32_t a;
    asm("{ .reg .u64 t; cvta.to.shared.u64 t, %1; cvt.u32.u64 %0, t; }" : "=r"(a) : "l"(p));
    return a;
}
#define CPA16(saddr, gptr) \
    asm volatile("cp.async.cg.shared.global [%0], [%1], 16;" :: "r"(saddr), "l"(gptr))
#define CPCOMMIT() asm volatile("cp.async.commit_group;")

// ---------------- weight pre-round ----------------
__global__ void roundw_kernel(const float* __restrict__ w, float* __restrict__ o, int n4) {
    int i = blockIdx.x * 256 + threadIdx.x;
    if (i < n4) {
        float4 v = ((const float4*)w)[i];
        v.x = rnd_tf32(v.x); v.y = rnd_tf32(v.y); v.z = rnd_tf32(v.z); v.w = rnd_tf32(v.w);
        ((float4*)o)[i] = v;
    }
}

// ---------------- LayerNorm (output rounded to tf32) ----------------
template<bool GATHER>
__global__ void ln_kernel(const float* __restrict__ x,
                          const float* __restrict__ g,
                          const float* __restrict__ b,
                          float* __restrict__ out) {
    int row  = blockIdx.x * 8 + (threadIdx.x >> 5);
    int lane = threadIdx.x & 31;
    int srow = GATHER ? winrow_to_xrow(row) : row;
    const float* src = x + (size_t)srow * DIMC;

    float v[6];
    float sum = 0.f;
#pragma unroll
    for (int t = 0; t < 6; t++) { v[t] = src[lane + 32 * t]; sum += v[t]; }
#pragma unroll
    for (int o = 16; o > 0; o >>= 1) sum += __shfl_xor_sync(0xffffffffu, sum, o);
    float mu = sum * (1.f / DIMC);
    float vs = 0.f;
#pragma unroll
    for (int t = 0; t < 6; t++) { float d = v[t] - mu; vs += d * d; }
#pragma unroll
    for (int o = 16; o > 0; o >>= 1) vs += __shfl_xor_sync(0xffffffffu, vs, o);
    float inv = rsqrtf(vs * (1.f / DIMC) + 1e-5f);

    float* dst = out + (size_t)row * DIMC;
#pragma unroll
    for (int t = 0; t < 6; t++) {
        int c = lane + 32 * t;
        dst[c] = rnd_tf32((v[t] - mu) * inv * g[c] + b[c]);
    }
}

// ---------------- attention (output rounded to tf32) ----------------
__global__ void attn_kernel(const float* __restrict__ qkv, float* __restrict__ out) {
    int win = blockIdx.x, head = blockIdx.y;
    int tid = threadIdx.x;

    __shared__ float sq[49][33], sk[49][33], sv[49][33];
    __shared__ float ss[49][49];

    const float* base = qkv + (size_t)win * 49 * (3 * DIMC) + head * HD;
    for (int idx = tid; idx < 49 * 8; idx += blockDim.x) {
        int n = idx >> 3, d4 = idx & 7;
        const float* row = base + (size_t)n * (3 * DIMC);
        float4 q4 = *(const float4*)(row + d4 * 4);
        float4 k4 = *(const float4*)(row + DIMC + d4 * 4);
        float4 v4 = *(const float4*)(row + 2 * DIMC + d4 * 4);
        sq[n][d4*4+0]=q4.x; sq[n][d4*4+1]=q4.y; sq[n][d4*4+2]=q4.z; sq[n][d4*4+3]=q4.w;
        sk[n][d4*4+0]=k4.x; sk[n][d4*4+1]=k4.y; sk[n][d4*4+2]=k4.z; sk[n][d4*4+3]=k4.w;
        sv[n][d4*4+0]=v4.x; sv[n][d4*4+1]=v4.y; sv[n][d4*4+2]=v4.z; sv[n][d4*4+3]=v4.w;
    }
    __syncthreads();

    const float scale = 0.17677669529663687f;
    for (int idx = tid; idx < 49 * 49; idx += blockDim.x) {
        int n = idx / 49, m = idx % 49;
        float acc = 0.f;
#pragma unroll
        for (int d = 0; d < HD; d++) acc += sq[n][d] * sk[m][d];
        ss[n][m] = acc * scale;
    }
    __syncthreads();

    if (tid < 49) {
        float mx = -1e30f;
#pragma unroll 7
        for (int m = 0; m < 49; m++) mx = fmaxf(mx, ss[tid][m]);
        float sum = 0.f;
#pragma unroll 7
        for (int m = 0; m < 49; m++) { float e = __expf(ss[tid][m] - mx); ss[tid][m] = e; sum += e; }
        float inv = 1.f / sum;
#pragma unroll 7
        for (int m = 0; m < 49; m++) ss[tid][m] *= inv;
    }
    __syncthreads();

    float* obase = out + (size_t)win * 49 * DIMC + head * HD;
    for (int idx = tid; idx < 49 * HD; idx += blockDim.x) {
        int n = idx >> 5, d = idx & 31;
        float acc = 0.f;
#pragma unroll 7
        for (int m = 0; m < 49; m++) acc += ss[n][m] * sv[m][d];
        obase[(size_t)n * DIMC + d] = rnd_tf32(acc);
    }
}

// ---------------- tf32 mma.sync GEMM, cp.async double-buffered ----------------
// Inputs A, B already tf32-rounded in gmem. BM=128, BN=64, BK=32.
// 128 threads = 4 warps (2m x 2n), warp tile 64x32 (mi4 x ni4 of m16n8k8).
// EPI: 0 bias; 1 bias+scatter; 2 bias+gelu(out rounded); 3 bias+residual
#define AS_W 4608   /* 128*36 words per buffer */
#define BS_W 2304   /* 32*72 words per buffer */
#define GEMM_SMEM ((2*AS_W + 2*BS_W) * 4)

template<int EPI, int N, int K>
__global__ __launch_bounds__(128, 4)
void mmagemm(const float* __restrict__ A, const float* __restrict__ Bw,
             const float* __restrict__ bias, const float* __restrict__ res,
             float* __restrict__ C) {
    constexpr int KT = K / 32;

    extern __shared__ float sm[];
    const uint32_t sbase = smem_u32(sm);
    int tid = threadIdx.x, lane = tid & 31, wid = tid >> 5;
    int warpm = (wid & 1) * 64;
    int warpn = (wid >> 1) * 32;
    int row0 = blockIdx.y * 128;
    int col0 = blockIdx.x * 64;

    float acc[4][4][4];
#pragma unroll
    for (int mi = 0; mi < 4; mi++)
#pragma unroll
        for (int ni = 0; ni < 4; ni++)
#pragma unroll
            for (int c = 0; c < 4; c++) acc[mi][ni][c] = 0.f;

    // load coordinates
    const int a_row = tid >> 3;            // 0..15, +16 per i (8 iters)
    const int a_kq  = (tid & 7) * 4;
    const int b_k   = tid >> 4;            // 0..7, +8 per i (4 iters)
    const int b_nq  = (tid & 15) * 4;

    const float* Ag = A + (size_t)(row0 + a_row) * K + a_kq;
    const float* Bg = Bw + (size_t)b_k * N + col0 + b_nq;
    uint32_t a_st = sbase + ((a_row * 36 + a_kq) << 2);
    uint32_t b_st = sbase + ((2 * AS_W + b_k * 72 + b_nq) << 2);

#define ISSUE(kt, buf) do { \
    const float* ap = Ag + (size_t)(kt) * 32; \
    uint32_t as_ = a_st + (buf) * (AS_W * 4); \
    _Pragma("unroll") \
    for (int i = 0; i < 8; i++) CPA16(as_ + i * (16 * 36 * 4), ap + (size_t)i * 16 * K); \
    const float* bp = Bg + (size_t)(kt) * 32 * N; \
    uint32_t bs_ = b_st + (buf) * (BS_W * 4); \
    _Pragma("unroll") \
    for (int i = 0; i < 4; i++) CPA16(bs_ + i * (8 * 72 * 4), bp + (size_t)i * 8 * N); \
    CPCOMMIT(); } while (0)

    ISSUE(0, 0);

#pragma unroll 1
    for (int kt = 0; kt < KT; kt++) {
        int cur = kt & 1;
        if (kt + 1 < KT) {
            ISSUE(kt + 1, cur ^ 1);
            asm volatile("cp.async.wait_group 1;");
        } else {
            asm volatile("cp.async.wait_group 0;");
        }
        __syncthreads();

        const float* as = sm + cur * AS_W;
        const float* bs = sm + 2 * AS_W + cur * BS_W;
#pragma unroll
        for (int ks = 0; ks < 4; ks++) {
            int kk = ks * 8 + (lane & 3);
            uint32_t af[4][4], bf[4][2];
#pragma unroll
            for (int mi = 0; mi < 4; mi++) {
                int r = warpm + mi * 16 + (lane >> 2);
                af[mi][0] = __float_as_uint(as[r * 36 + kk]);
                af[mi][1] = __float_as_uint(as[(r + 8) * 36 + kk]);
                af[mi][2] = __float_as_uint(as[r * 36 + kk + 4]);
                af[mi][3] = __float_as_uint(as[(r + 8) * 36 + kk + 4]);
            }
#pragma unroll
            for (int ni = 0; ni < 4; ni++) {
                int n = warpn + ni * 8 + (lane >> 2);
                bf[ni][0] = __float_as_uint(bs[kk * 72 + n]);
                bf[ni][1] = __float_as_uint(bs[(kk + 4) * 72 + n]);
            }
#pragma unroll
            for (int mi = 0; mi < 4; mi++)
#pragma unroll
                for (int ni = 0; ni < 4; ni++) {
                    float* c = acc[mi][ni];
                    asm volatile(
                        "mma.sync.aligned.m16n8k8.row.col.f32.tf32.tf32.f32 "
                        "{%0,%1,%2,%3}, {%4,%5,%6,%7}, {%8,%9}, {%0,%1,%2,%3};"
                        : "+f"(c[0]), "+f"(c[1]), "+f"(c[2]), "+f"(c[3])
                        : "r"(af[mi][0]), "r"(af[mi][1]), "r"(af[mi][2]), "r"(af[mi][3]),
                          "r"(bf[ni][0]), "r"(bf[ni][1]));
                }
        }
        __syncthreads();
    }
#undef ISSUE

    // ---- epilogue ----
#pragma unroll
    for (int mi = 0; mi < 4; mi++)
#pragma unroll
        for (int ni = 0; ni < 4; ni++)
#pragma unroll
            for (int half = 0; half < 2; half++) {
                int r = row0 + warpm + mi * 16 + (lane >> 2) + half * 8;
                int cg = col0 + warpn + ni * 8 + 2 * (lane & 3);
                float v0 = acc[mi][ni][half * 2 + 0] + bias[cg];
                float v1 = acc[mi][ni][half * 2 + 1] + bias[cg + 1];
                if (EPI == 2) {
                    v0 = rnd_tf32(0.5f * v0 * (1.f + erff(v0 * 0.70710678118654752f)));
                    v1 = rnd_tf32(0.5f * v1 * (1.f + erff(v1 * 0.70710678118654752f)));
                }
                if (EPI == 3) {
                    v0 += res[(size_t)r * N + cg];
                    v1 += res[(size_t)r * N + cg + 1];
                }
                int dr = (EPI == 1) ? winrow_to_xrow(r) : r;
                *(float2*)(C + (size_t)dr * N + cg) = make_float2(v0, v1);
            }
}

// ---------------- launch ----------------
extern "C" void kernel_launch(void* const* d_in, const int* in_sizes, int n_in,
                              void* d_out, int out_size) {
    const float* x      = (const float*)d_in[0];
    const float* qkv_w  = (const float*)d_in[1];
    const float* qkv_b  = (const float*)d_in[2];
    const float* proj_w = (const float*)d_in[3];
    const float* proj_b = (const float*)d_in[4];
    const float* g1     = (const float*)d_in[5];
    const float* be1    = (const float*)d_in[6];
    const float* g2     = (const float*)d_in[7];
    const float* be2    = (const float*)d_in[8];
    const float* w1     = (const float*)d_in[9];
    const float* b1     = (const float*)d_in[10];
    const float* w2     = (const float*)d_in[11];
    const float* b2     = (const float*)d_in[12];
    float* out = (float*)d_out;

    float *xn, *qkv, *attn, *xbuf, *hid, *wbuf;
    cudaGetSymbolAddress((void**)&xn,   g_xn);
    cudaGetSymbolAddress((void**)&qkv,  g_qkv);
    cudaGetSymbolAddress((void**)&attn, g_attn);
    cudaGetSymbolAddress((void**)&xbuf, g_x);
    cudaGetSymbolAddress((void**)&hid,  g_hid);
    cudaGetSymbolAddress((void**)&wbuf, g_w);

    float* rw_qkv  = wbuf;
    float* rw_proj = rw_qkv + DIMC * 3 * DIMC;
    float* rw_w1   = rw_proj + DIMC * DIMC;
    float* rw_w2   = rw_w1 + DIMC * HIDDEN;

    cudaFuncSetAttribute(mmagemm<0, 576, 192>, cudaFuncAttributeMaxDynamicSharedMemorySize, GEMM_SMEM);
    cudaFuncSetAttribute(mmagemm<1, 192, 192>, cudaFuncAttributeMaxDynamicSharedMemorySize, GEMM_SMEM);
    cudaFuncSetAttribute(mmagemm<2, 768, 192>, cudaFuncAttributeMaxDynamicSharedMemorySize, GEMM_SMEM);
    cudaFuncSetAttribute(mmagemm<3, 192, 768>, cudaFuncAttributeMaxDynamicSharedMemorySize, GEMM_SMEM);

    const int MT = MROWS / 128;   // 784

    // 0) pre-round weights to tf32
    roundw_kernel<<<(DIMC*3*DIMC/4 + 255)/256, 256>>>(qkv_w, rw_qkv, DIMC*3*DIMC/4);
    roundw_kernel<<<(DIMC*DIMC/4 + 255)/256, 256>>>(proj_w, rw_proj, DIMC*DIMC/4);
    roundw_kernel<<<(DIMC*HIDDEN/4 + 255)/256, 256>>>(w1, rw_w1, DIMC*HIDDEN/4);
    roundw_kernel<<<(HIDDEN*DIMC/4 + 255)/256, 256>>>(w2, rw_w2, HIDDEN*DIMC/4);

    // 1) shift-gather + LN1 (rounded out)
    ln_kernel<true><<<MROWS / 8, 256>>>(x, g1, be1, xn);
    // 2) QKV GEMM
    mmagemm<0, 576, 192><<<dim3(9, MT), 128, GEMM_SMEM>>>(xn, rw_qkv, qkv_b, nullptr, qkv);
    // 3) windowed attention (rounded out)
    attn_kernel<<<dim3(NWIN, NHEAD), 128>>>(qkv, attn);
    // 4) proj GEMM + reverse-shift scatter
    mmagemm<1, 192, 192><<<dim3(3, MT), 128, GEMM_SMEM>>>(attn, rw_proj, proj_b, nullptr, xbuf);
    // 5) LN2 (rounded out)
    ln_kernel<false><<<MROWS / 8, 256>>>(xbuf, g2, be2, xn);
    // 6) FC1 + GELU (rounded out)
    mmagemm<2, 768, 192><<<dim3(12, MT), 128, GEMM_SMEM>>>(xn, rw_w1, b1, nullptr, hid);
    // 7) FC2 + residual
    mmagemm<3, 192, 768><<<dim3(3, MT), 128, GEMM_SMEM>>>(hid, rw_w2, b2, xbuf, out);
}